// round 1
// baseline (speedup 1.0000x reference)
#include <cuda_runtime.h>
#include <cstdint>

#define NPTS   65536
#define NQ     1024
#define NBATCH 2
#define NS1    32
#define NS2    64
#define NOUT   128

// Per-query neighbor lists: [list1(32) | list2(64)] per query, 2048 queries.
static __device__ int g_lists[NBATCH * NQ * 96];

__device__ __forceinline__ float sq3_rn(float x, float y, float z) {
    return __fadd_rn(__fadd_rn(__fmul_rn(x, x), __fmul_rn(y, y)), __fmul_rn(z, z));
}

// ---------------------------------------------------------------------------
// Kernel 1: one warp per query. Sequential scan of pts1 in index order with
// ordered ballot-append into the two neighbor lists; early exit when both full.
// Distance formula matches the reference: (q2 + p2) - 2*dot, all ops _rn to
// suppress fma contraction (classification boundary sensitivity).
// ---------------------------------------------------------------------------
__global__ __launch_bounds__(256) void scan_kernel(const float* __restrict__ pts) {
    const int lane = threadIdx.x & 31;
    const int wid  = threadIdx.x >> 5;
    const int q    = blockIdx.x * 8 + wid;          // 0..2047
    if (q >= NBATCH * NQ) return;
    const int b = q >> 10;
    const int m = q & 1023;
    const int fi = (4 + 8 * (m >> 5)) * 256 + (4 + 8 * (m & 31));

    const float* P = pts + (size_t)b * NPTS * 3;
    const float qx = __ldg(P + 3 * fi + 0);
    const float qy = __ldg(P + 3 * fi + 1);
    const float qz = __ldg(P + 3 * fi + 2);
    const float q2 = sq3_rn(qx, qy, qz);

    const float R1SQ = (float)(0.1 * 0.1);
    const float R2SQ = (float)(0.2 * 0.2);

    __shared__ int s_l[8][96];
    int* l1 = s_l[wid];
    int* l2 = s_l[wid] + NS1;

    int cnt1 = 0, cnt2 = 0;
    const unsigned lt = (1u << lane) - 1u;

    for (int base = 0; base < NPTS; base += 64) {
        const int iA = base + lane;
        const int iB = iA + 32;
        // 6 independent loads in flight per warp-iteration
        float ax = __ldg(P + 3 * iA + 0);
        float ay = __ldg(P + 3 * iA + 1);
        float az = __ldg(P + 3 * iA + 2);
        float bx = __ldg(P + 3 * iB + 0);
        float by = __ldg(P + 3 * iB + 1);
        float bz = __ldg(P + 3 * iB + 2);

        float dotA = __fadd_rn(__fadd_rn(__fmul_rn(ax, qx), __fmul_rn(ay, qy)), __fmul_rn(az, qz));
        float dotB = __fadd_rn(__fadd_rn(__fmul_rn(bx, qx), __fmul_rn(by, qy)), __fmul_rn(bz, qz));
        float d2A = __fadd_rn(__fadd_rn(q2, sq3_rn(ax, ay, az)), __fmul_rn(-2.0f, dotA));
        float d2B = __fadd_rn(__fadd_rn(q2, sq3_rn(bx, by, bz)), __fmul_rn(-2.0f, dotB));

        bool h1A = d2A < R1SQ, h2A = d2A < R2SQ;
        bool h1B = d2B < R1SQ, h2B = d2B < R2SQ;
        unsigned m1A = __ballot_sync(0xffffffffu, h1A);
        unsigned m2A = __ballot_sync(0xffffffffu, h2A);
        unsigned m1B = __ballot_sync(0xffffffffu, h1B);
        unsigned m2B = __ballot_sync(0xffffffffu, h2B);

        if (h1A) { int p = cnt1 + __popc(m1A & lt); if (p < NS1) l1[p] = iA; }
        if (h2A) { int p = cnt2 + __popc(m2A & lt); if (p < NS2) l2[p] = iA; }
        int c1A = cnt1 + __popc(m1A);
        int c2A = cnt2 + __popc(m2A);
        if (h1B) { int p = c1A + __popc(m1B & lt); if (p < NS1) l1[p] = iB; }
        if (h2B) { int p = c2A + __popc(m2B & lt); if (p < NS2) l2[p] = iB; }
        cnt1 = c1A + __popc(m1B);
        cnt2 = c2A + __popc(m2B);
        if (cnt1 >= NS1 && cnt2 >= NS2) break;
    }
    __syncwarp();

    // Pad with the first hit (reference: invalid entries -> idx[...,0], or 0 if none)
    const int c1 = min(cnt1, NS1);
    const int c2 = min(cnt2, NS2);
    const int f1 = (c1 > 0) ? l1[0] : 0;
    const int f2 = (c2 > 0) ? l2[0] : 0;
    for (int j = c1 + lane; j < NS1; j += 32) l1[j] = f1;
    for (int j = c2 + lane; j < NS2; j += 32) l2[j] = f2;
    __syncwarp();

    int* dst = g_lists + q * 96;
    for (int j = lane; j < 96; j += 32) dst[j] = s_l[wid][j];
}

// ---------------------------------------------------------------------------
// Kernel 2: one warp per query. Gather neighbors, tiny MLP (6->16->32) + ReLU
// with BN-style scale (inv = 1/sqrt(1+eps)), max-pool over neighbors in
// registers + warp shuffle reduce, then fused 64->128 linear from transposed
// shared-memory w3.
// ---------------------------------------------------------------------------
#define INVC 0.9999950000374997f

template <int S>
__device__ __forceinline__ void run_branch(
    const float* __restrict__ P, float qx, float qy, float qz,
    const int* __restrict__ list, int lane,
    const float* __restrict__ sA, const float* __restrict__ scA, const float* __restrict__ biA,
    const float* __restrict__ sB, const float* __restrict__ scB, const float* __restrict__ biB,
    float fmax_[32])
{
    float f[32];
#pragma unroll
    for (int o = 0; o < 32; o++) f[o] = 0.0f;   // post-relu values are >= 0

#pragma unroll
    for (int sblk = 0; sblk < S; sblk += 32) {
        const int s = sblk + lane;
        const int idx = __ldg(list + s);
        const float gx = __ldg(P + 3 * idx + 0);
        const float gy = __ldg(P + 3 * idx + 1);
        const float gz = __ldg(P + 3 * idx + 2);
        const float x0 = gx - qx, x1 = gy - qy, x2 = gz - qz;

        float a[16];
#pragma unroll
        for (int o = 0; o < 16; o++) {
            const float* w = sA + o * 6;
            float y = x0 * w[0];
            y = fmaf(x1, w[1], y);
            y = fmaf(x2, w[2], y);
            y = fmaf(gx, w[3], y);
            y = fmaf(gy, w[4], y);
            y = fmaf(gz, w[5], y);
            a[o] = fmaxf(fmaf(y, scA[o], biA[o]), 0.0f);
        }
#pragma unroll
        for (int o = 0; o < 32; o++) {
            const float* w = sB + o * 16;
            float y = 0.0f;
#pragma unroll
            for (int c = 0; c < 16; c++) y = fmaf(a[c], w[c], y);
            f[o] = fmaxf(f[o], fmaxf(fmaf(y, scB[o], biB[o]), 0.0f));
        }
    }
#pragma unroll
    for (int o = 0; o < 32; o++) {
        float v = f[o];
        v = fmaxf(v, __shfl_xor_sync(0xffffffffu, v, 16));
        v = fmaxf(v, __shfl_xor_sync(0xffffffffu, v, 8));
        v = fmaxf(v, __shfl_xor_sync(0xffffffffu, v, 4));
        v = fmaxf(v, __shfl_xor_sync(0xffffffffu, v, 2));
        v = fmaxf(v, __shfl_xor_sync(0xffffffffu, v, 1));
        fmax_[o] = v;
    }
}

__global__ __launch_bounds__(256) void mlp_kernel(
    const float* __restrict__ pts,
    const float* __restrict__ w1a, const float* __restrict__ g1a, const float* __restrict__ b1a,
    const float* __restrict__ w1b, const float* __restrict__ g1b, const float* __restrict__ b1b,
    const float* __restrict__ w2a, const float* __restrict__ g2a, const float* __restrict__ b2a,
    const float* __restrict__ w2b, const float* __restrict__ g2b, const float* __restrict__ b2b,
    const float* __restrict__ w3,  const float* __restrict__ b3,
    float* __restrict__ out)
{
    __shared__ float s_w1a[96],  s_w2a[96];
    __shared__ float s_w1b[512], s_w2b[512];
    __shared__ float s_sc1a[16], s_bi1a[16], s_sc2a[16], s_bi2a[16];
    __shared__ float s_sc1b[32], s_bi1b[32], s_sc2b[32], s_bi2b[32];
    __shared__ float s_w3t[64 * 129];   // transposed + padded: conflict-free loads

    const int tid = threadIdx.x;
    for (int i = tid; i < 96; i += 256)  { s_w1a[i] = w1a[i]; s_w2a[i] = w2a[i]; }
    for (int i = tid; i < 512; i += 256) { s_w1b[i] = w1b[i]; s_w2b[i] = w2b[i]; }
    if (tid < 16) {
        s_sc1a[tid] = g1a[tid] * INVC; s_bi1a[tid] = b1a[tid];
        s_sc2a[tid] = g2a[tid] * INVC; s_bi2a[tid] = b2a[tid];
    } else if (tid < 48) {
        const int i = tid - 16;
        s_sc1b[i] = g1b[i] * INVC; s_bi1b[i] = b1b[i];
        s_sc2b[i] = g2b[i] * INVC; s_bi2b[i] = b2b[i];
    }
    for (int i = tid; i < NOUT * 64; i += 256) {
        const int o = i >> 6, c = i & 63;
        s_w3t[c * 129 + o] = w3[i];
    }
    __syncthreads();

    const int lane = tid & 31;
    const int wid  = tid >> 5;
    const int q    = blockIdx.x * 8 + wid;
    if (q >= NBATCH * NQ) return;
    const int b = q >> 10;
    const int m = q & 1023;
    const int fi = (4 + 8 * (m >> 5)) * 256 + (4 + 8 * (m & 31));

    const float* P = pts + (size_t)b * NPTS * 3;
    const float qx = __ldg(P + 3 * fi + 0);
    const float qy = __ldg(P + 3 * fi + 1);
    const float qz = __ldg(P + 3 * fi + 2);

    const int* l1 = g_lists + q * 96;
    const int* l2 = l1 + NS1;

    float fm1[32], fm2[32];
    run_branch<NS1>(P, qx, qy, qz, l1, lane, s_w1a, s_sc1a, s_bi1a, s_w1b, s_sc1b, s_bi1b, fm1);
    run_branch<NS2>(P, qx, qy, qz, l2, lane, s_w2a, s_sc2a, s_bi2a, s_w2b, s_sc2b, s_bi2b, fm2);

    const size_t ob = (size_t)q * NOUT;
#pragma unroll
    for (int k = 0; k < 4; k++) {
        const int o = lane + 32 * k;
        float acc = __ldg(b3 + o);
#pragma unroll
        for (int c = 0; c < 32; c++) acc = fmaf(fm1[c], s_w3t[c * 129 + o], acc);
#pragma unroll
        for (int c = 0; c < 32; c++) acc = fmaf(fm2[c], s_w3t[(c + 32) * 129 + o], acc);
        out[ob + o] = acc;
    }
}

extern "C" void kernel_launch(void* const* d_in, const int* in_sizes, int n_in,
                              void* d_out, int out_size) {
    const float* pts = (const float*)d_in[0];
    const float* w1a = (const float*)d_in[1];
    const float* g1a = (const float*)d_in[2];
    const float* b1a = (const float*)d_in[3];
    const float* w1b = (const float*)d_in[4];
    const float* g1b = (const float*)d_in[5];
    const float* b1b = (const float*)d_in[6];
    const float* w2a = (const float*)d_in[7];
    const float* g2a = (const float*)d_in[8];
    const float* b2a = (const float*)d_in[9];
    const float* w2b = (const float*)d_in[10];
    const float* g2b = (const float*)d_in[11];
    const float* b2b = (const float*)d_in[12];
    const float* w3  = (const float*)d_in[13];
    const float* b3  = (const float*)d_in[14];
    float* out = (float*)d_out;

    const int nWarps = NBATCH * NQ;          // 2048 queries
    const int blocks = nWarps / 8;           // 8 warps (queries) per CTA

    scan_kernel<<<blocks, 256>>>(pts);
    mlp_kernel<<<blocks, 256>>>(pts, w1a, g1a, b1a, w1b, g1b, b1b,
                                w2a, g2a, b2a, w2b, g2b, b2b, w3, b3, out);
}

// round 2
// speedup vs baseline: 1.5617x; 1.5617x over previous
#include <cuda_runtime.h>
#include <cstdint>

#define NPTS   65536
#define NQ     1024
#define NBATCH 2
#define NS1    32
#define NS2    64
#define NOUT   128
#define TP     2048   // points per shared tile in scan kernel

// Per-query neighbor lists: [list1(32) | list2(64)] per query, 2048 queries.
static __device__ int g_lists[NBATCH * NQ * 96];

__device__ __forceinline__ float sq3_rn(float x, float y, float z) {
    return __fadd_rn(__fadd_rn(__fmul_rn(x, x), __fmul_rn(y, y)), __fmul_rn(z, z));
}

__device__ __forceinline__ int query_flat_index(int q, int& b) {
    b = q >> 10;
    const int m = q & 1023;
    return (4 + 8 * (m >> 5)) * 256 + (4 + 8 * (m & 31));
}

// ---------------------------------------------------------------------------
// Kernel 1: block = 8 warps = 8 queries. The block streams pts1 in 2048-point
// tiles staged in smem as float4(x,y,z,|p|^2); each warp scans tiles in index
// order (append order == global index order), early-exits when both lists are
// full; block breaks when all 8 warps are done (__syncthreads_and).
// Distance formula matches the reference: (q2 + p2) - 2*dot, all ops _rn.
// ---------------------------------------------------------------------------
__global__ __launch_bounds__(256) void scan_kernel(const float* __restrict__ pts) {
    __shared__ float4 s_p[TP];
    __shared__ int    s_l[8][96];

    const int tid  = threadIdx.x;
    const int lane = tid & 31;
    const int wid  = tid >> 5;
    const int q    = blockIdx.x * 8 + wid;          // 0..2047
    int b;
    const int fi = query_flat_index(q, b);

    const float* P = pts + (size_t)b * NPTS * 3;
    const float qx = __ldg(P + 3 * fi + 0);
    const float qy = __ldg(P + 3 * fi + 1);
    const float qz = __ldg(P + 3 * fi + 2);
    const float q2 = sq3_rn(qx, qy, qz);

    const float R1SQ = (float)(0.1 * 0.1);
    const float R2SQ = (float)(0.2 * 0.2);

    int* l1 = s_l[wid];
    int* l2 = s_l[wid] + NS1;

    int  cnt1 = 0, cnt2 = 0;
    bool done = false;
    const unsigned lt = (1u << lane) - 1u;

    // All 8 blocks per query-group share batch b (8 queries span one batch
    // except possibly at the boundary block — q/1024 is uniform per block
    // since 1024 % 8 == 0, so P is uniform across the block).
    const float* PB = pts + (size_t)(blockIdx.x * 8 / NQ) * NPTS * 3;

    for (int base = 0; base < NPTS; base += TP) {
        // Sync #1: previous tile's consumers finished, and done-flags current.
        if (__syncthreads_and(done ? 1 : 0)) break;

        // Stage tile: thread t loads points base+t, base+t+256, ...
        #pragma unroll
        for (int j = tid; j < TP; j += 256) {
            const int p = base + j;
            const float x = __ldg(PB + 3 * p + 0);
            const float y = __ldg(PB + 3 * p + 1);
            const float z = __ldg(PB + 3 * p + 2);
            s_p[j] = make_float4(x, y, z, sq3_rn(x, y, z));
        }
        __syncthreads();   // Sync #2: tile visible.

        if (!done) {
            for (int g = 0; g < TP; g += 32) {
                const float4 pt = s_p[g + lane];
                const float dot = __fadd_rn(__fadd_rn(__fmul_rn(pt.x, qx), __fmul_rn(pt.y, qy)),
                                            __fmul_rn(pt.z, qz));
                const float d2  = __fadd_rn(__fadd_rn(q2, pt.w), __fmul_rn(-2.0f, dot));
                const bool h2 = d2 < R2SQ;
                const unsigned m2 = __ballot_sync(0xffffffffu, h2);
                if (m2) {   // h1 implies h2, so m2==0 -> nothing to do
                    const bool h1 = d2 < R1SQ;
                    const unsigned m1 = __ballot_sync(0xffffffffu, h1);
                    const int idx = base + g + lane;
                    if (h1) { const int p = cnt1 + __popc(m1 & lt); if (p < NS1) l1[p] = idx; }
                    if (h2) { const int p = cnt2 + __popc(m2 & lt); if (p < NS2) l2[p] = idx; }
                    cnt1 += __popc(m1);
                    cnt2 += __popc(m2);
                    if (cnt1 >= NS1 && cnt2 >= NS2) { done = true; break; }
                }
            }
        }
    }
    __syncwarp();

    // Pad with the first hit (reference: invalid entries -> idx[...,0], or 0).
    const int c1 = min(cnt1, NS1);
    const int c2 = min(cnt2, NS2);
    const int f1 = (c1 > 0) ? l1[0] : 0;
    const int f2 = (c2 > 0) ? l2[0] : 0;
    for (int j = c1 + lane; j < NS1; j += 32) l1[j] = f1;
    for (int j = c2 + lane; j < NS2; j += 32) l2[j] = f2;
    __syncwarp();

    int* dst = g_lists + q * 96;
    for (int j = lane; j < 96; j += 32) dst[j] = s_l[wid][j];
}

// ---------------------------------------------------------------------------
// Kernel 2: one warp per query. All neighbor indices and coordinates are
// prefetched up front (single exposed memory latency), then the two tiny
// MLPs (6->16->32, relu, BN-scale) + max-pool run from registers/smem.
// Final 64->128 linear accumulated per-branch from transposed smem w3.
// ---------------------------------------------------------------------------
#define INVC 0.9999950000374997f

__device__ __forceinline__ void mlp_point(
    float gx, float gy, float gz, float qx, float qy, float qz,
    const float* __restrict__ sA, const float* __restrict__ scA, const float* __restrict__ biA,
    const float* __restrict__ sB, const float* __restrict__ scB, const float* __restrict__ biB,
    float f[32])
{
    const float x0 = gx - qx, x1 = gy - qy, x2 = gz - qz;
    float a[16];
#pragma unroll
    for (int o = 0; o < 16; o++) {
        const float* w = sA + o * 6;
        float y = x0 * w[0];
        y = fmaf(x1, w[1], y);
        y = fmaf(x2, w[2], y);
        y = fmaf(gx, w[3], y);
        y = fmaf(gy, w[4], y);
        y = fmaf(gz, w[5], y);
        a[o] = fmaxf(fmaf(y, scA[o], biA[o]), 0.0f);
    }
#pragma unroll
    for (int o = 0; o < 32; o++) {
        const float* w = sB + o * 16;
        float y = 0.0f;
#pragma unroll
        for (int c = 0; c < 16; c++) y = fmaf(a[c], w[c], y);
        f[o] = fmaxf(f[o], fmaxf(fmaf(y, scB[o], biB[o]), 0.0f));
    }
}

__device__ __forceinline__ void warp_max32(float f[32]) {
#pragma unroll
    for (int o = 0; o < 32; o++) {
        float v = f[o];
        v = fmaxf(v, __shfl_xor_sync(0xffffffffu, v, 16));
        v = fmaxf(v, __shfl_xor_sync(0xffffffffu, v, 8));
        v = fmaxf(v, __shfl_xor_sync(0xffffffffu, v, 4));
        v = fmaxf(v, __shfl_xor_sync(0xffffffffu, v, 2));
        v = fmaxf(v, __shfl_xor_sync(0xffffffffu, v, 1));
        f[o] = v;
    }
}

__global__ __launch_bounds__(256) void mlp_kernel(
    const float* __restrict__ pts,
    const float* __restrict__ w1a, const float* __restrict__ g1a, const float* __restrict__ b1a,
    const float* __restrict__ w1b, const float* __restrict__ g1b, const float* __restrict__ b1b,
    const float* __restrict__ w2a, const float* __restrict__ g2a, const float* __restrict__ b2a,
    const float* __restrict__ w2b, const float* __restrict__ g2b, const float* __restrict__ b2b,
    const float* __restrict__ w3,  const float* __restrict__ b3,
    float* __restrict__ out)
{
    __shared__ float s_w1a[96],  s_w2a[96];
    __shared__ float s_w1b[512], s_w2b[512];
    __shared__ float s_sc1a[16], s_bi1a[16], s_sc2a[16], s_bi2a[16];
    __shared__ float s_sc1b[32], s_bi1b[32], s_sc2b[32], s_bi2b[32];
    __shared__ float s_w3t[64 * 129];   // transposed + padded

    const int tid = threadIdx.x;
    for (int i = tid; i < 96; i += 256)  { s_w1a[i] = w1a[i]; s_w2a[i] = w2a[i]; }
    for (int i = tid; i < 512; i += 256) { s_w1b[i] = w1b[i]; s_w2b[i] = w2b[i]; }
    if (tid < 16) {
        s_sc1a[tid] = g1a[tid] * INVC; s_bi1a[tid] = b1a[tid];
        s_sc2a[tid] = g2a[tid] * INVC; s_bi2a[tid] = b2a[tid];
    } else if (tid < 48) {
        const int i = tid - 16;
        s_sc1b[i] = g1b[i] * INVC; s_bi1b[i] = b1b[i];
        s_sc2b[i] = g2b[i] * INVC; s_bi2b[i] = b2b[i];
    }
    for (int i = tid; i < NOUT * 64; i += 256) {
        const int o = i >> 6, c = i & 63;
        s_w3t[c * 129 + o] = w3[i];
    }
    __syncthreads();

    const int lane = tid & 31;
    const int wid  = tid >> 5;
    const int q    = blockIdx.x * 8 + wid;
    int b;
    const int fi = query_flat_index(q, b);

    const float* P = pts + (size_t)b * NPTS * 3;
    const float qx = __ldg(P + 3 * fi + 0);
    const float qy = __ldg(P + 3 * fi + 1);
    const float qz = __ldg(P + 3 * fi + 2);

    const int* lst = g_lists + q * 96;

    // ---- Prefetch: all 3 index words, then all 9 coordinates, in flight at once.
    const int i0 = __ldg(lst + lane);            // list1 chunk
    const int i1 = __ldg(lst + NS1 + lane);      // list2 chunk 0
    const int i2 = __ldg(lst + NS1 + 32 + lane); // list2 chunk 1
    const float p0x = __ldg(P + 3 * i0 + 0), p0y = __ldg(P + 3 * i0 + 1), p0z = __ldg(P + 3 * i0 + 2);
    const float p1x = __ldg(P + 3 * i1 + 0), p1y = __ldg(P + 3 * i1 + 1), p1z = __ldg(P + 3 * i1 + 2);
    const float p2x = __ldg(P + 3 * i2 + 0), p2y = __ldg(P + 3 * i2 + 1), p2z = __ldg(P + 3 * i2 + 2);

    const size_t ob = (size_t)q * NOUT;
    float acc[4];
#pragma unroll
    for (int k = 0; k < 4; k++) acc[k] = __ldg(b3 + lane + 32 * k);

    // ---- Branch 1 (S=32)
    {
        float f[32];
#pragma unroll
        for (int o = 0; o < 32; o++) f[o] = 0.0f;
        mlp_point(p0x, p0y, p0z, qx, qy, qz, s_w1a, s_sc1a, s_bi1a, s_w1b, s_sc1b, s_bi1b, f);
        warp_max32(f);
#pragma unroll
        for (int k = 0; k < 4; k++) {
            const int o = lane + 32 * k;
            float a = acc[k];
#pragma unroll
            for (int c = 0; c < 32; c++) a = fmaf(f[c], s_w3t[c * 129 + o], a);
            acc[k] = a;
        }
    }
    // ---- Branch 2 (S=64)
    {
        float f[32];
#pragma unroll
        for (int o = 0; o < 32; o++) f[o] = 0.0f;
        mlp_point(p1x, p1y, p1z, qx, qy, qz, s_w2a, s_sc2a, s_bi2a, s_w2b, s_sc2b, s_bi2b, f);
        mlp_point(p2x, p2y, p2z, qx, qy, qz, s_w2a, s_sc2a, s_bi2a, s_w2b, s_sc2b, s_bi2b, f);
        warp_max32(f);
#pragma unroll
        for (int k = 0; k < 4; k++) {
            const int o = lane + 32 * k;
            float a = acc[k];
#pragma unroll
            for (int c = 0; c < 32; c++) a = fmaf(f[c], s_w3t[(c + 32) * 129 + o], a);
            acc[k] = a;
        }
    }
#pragma unroll
    for (int k = 0; k < 4; k++) out[ob + lane + 32 * k] = acc[k];
}

extern "C" void kernel_launch(void* const* d_in, const int* in_sizes, int n_in,
                              void* d_out, int out_size) {
    const float* pts = (const float*)d_in[0];
    const float* w1a = (const float*)d_in[1];
    const float* g1a = (const float*)d_in[2];
    const float* b1a = (const float*)d_in[3];
    const float* w1b = (const float*)d_in[4];
    const float* g1b = (const float*)d_in[5];
    const float* b1b = (const float*)d_in[6];
    const float* w2a = (const float*)d_in[7];
    const float* g2a = (const float*)d_in[8];
    const float* b2a = (const float*)d_in[9];
    const float* w2b = (const float*)d_in[10];
    const float* g2b = (const float*)d_in[11];
    const float* b2b = (const float*)d_in[12];
    const float* w3  = (const float*)d_in[13];
    const float* b3  = (const float*)d_in[14];
    float* out = (float*)d_out;

    const int blocks = NBATCH * NQ / 8;     // 256 blocks, 8 queries each

    scan_kernel<<<blocks, 256>>>(pts);
    mlp_kernel<<<blocks, 256>>>(pts, w1a, g1a, b1a, w1b, g1b, b1b,
                                w2a, g2a, b2a, w2b, g2b, b2b, w3, b3, out);
}

// round 3
// speedup vs baseline: 1.9063x; 1.2206x over previous
#include <cuda_runtime.h>
#include <cstdint>

#define NPTS   65536
#define NQ     1024
#define NBATCH 2
#define NS1    32
#define NS2    64
#define NOUT   128
#define CAP    16384                 // phase-1 scan cap
#define SEG    ((NPTS - CAP) / 8)   // 6144 points per phase-2 warp

static __device__ float4 g_pts4[NBATCH * NPTS];          // (x,y,z,|p|^2)
static __device__ int    g_lists[NBATCH * NQ * 96];      // [l1(32)|l2(64)] per query
static __device__ int    g_state[NBATCH * NQ * 2];       // capped cnt1, cnt2

__device__ __forceinline__ float sq3_rn(float x, float y, float z) {
    return __fadd_rn(__fadd_rn(__fmul_rn(x, x), __fmul_rn(y, y)), __fmul_rn(z, z));
}

__device__ __forceinline__ int query_flat_index(int q, int& b) {
    b = q >> 10;
    const int m = q & 1023;
    return (4 + 8 * (m >> 5)) * 256 + (4 + 8 * (m & 31));
}

#define R1SQ 0.010000001f   /* (float)(0.1*0.1) */
#define R2SQ 0.040000003f   /* (float)(0.2*0.2) */
// Use exactly-rounded constants via computation instead, to be safe:
__device__ __forceinline__ void radii(float& r1sq, float& r2sq) {
    r1sq = __fmul_rn(0.1f, 0.1f);
    r2sq = __fmul_rn(0.2f, 0.2f);
}

// Evaluate one 32-point group; append ordered hits. m2 is warp-uniform.
__device__ __forceinline__ void eval_group(
    float4 pt, float qx, float qy, float qz, float q2,
    float r1sq, float r2sq, int idx, unsigned lt,
    int& cnt1, int& cnt2, int* __restrict__ l1, int* __restrict__ l2)
{
    const float dot = __fadd_rn(__fadd_rn(__fmul_rn(pt.x, qx), __fmul_rn(pt.y, qy)),
                                __fmul_rn(pt.z, qz));
    const float d2  = __fadd_rn(__fadd_rn(q2, pt.w), __fmul_rn(-2.0f, dot));
    const bool h2 = d2 < r2sq;
    const unsigned m2 = __ballot_sync(0xffffffffu, h2);
    if (m2) {
        const bool h1 = d2 < r1sq;
        const unsigned m1 = __ballot_sync(0xffffffffu, h1);
        if (h1) { const int p = cnt1 + __popc(m1 & lt); if (p < NS1) l1[p] = idx; }
        if (h2) { const int p = cnt2 + __popc(m2 & lt); if (p < NS2) l2[p] = idx; }
        cnt1 += __popc(m1);
        cnt2 += __popc(m2);
    }
}

// ---------------------------------------------------------------------------
// Kernel 0: pack pts -> float4(x,y,z,|p|^2)
// ---------------------------------------------------------------------------
__global__ __launch_bounds__(256) void pack_kernel(const float* __restrict__ pts) {
    const int i = blockIdx.x * 256 + threadIdx.x;   // 0 .. 131071
    const float x = __ldg(pts + 3 * i + 0);
    const float y = __ldg(pts + 3 * i + 1);
    const float z = __ldg(pts + 3 * i + 2);
    g_pts4[i] = make_float4(x, y, z, sq3_rn(x, y, z));
}

// ---------------------------------------------------------------------------
// Kernel 1: phase-1 scan. One independent warp per query, first CAP points,
// 4-deep unrolled LDG.128 stream, early exit when both lists full.
// ---------------------------------------------------------------------------
__global__ __launch_bounds__(256) void scan1_kernel() {
    __shared__ int s_l[8][96];

    const int lane = threadIdx.x & 31;
    const int wid  = threadIdx.x >> 5;
    const int q    = blockIdx.x * 8 + wid;          // 0..2047
    int b;
    const int fi = query_flat_index(q, b);

    const float4* __restrict__ P4 = g_pts4 + (size_t)b * NPTS;
    const float4 qp = __ldg(P4 + fi);
    const float qx = qp.x, qy = qp.y, qz = qp.z, q2 = qp.w;
    float r1sq, r2sq; radii(r1sq, r2sq);

    int* l1 = s_l[wid];
    int* l2 = s_l[wid] + NS1;
    int cnt1 = 0, cnt2 = 0;
    const unsigned lt = (1u << lane) - 1u;

    for (int base = 0; base < CAP; base += 128) {
        const float4 p0 = __ldg(P4 + base + lane);
        const float4 p1 = __ldg(P4 + base + 32 + lane);
        const float4 p2 = __ldg(P4 + base + 64 + lane);
        const float4 p3 = __ldg(P4 + base + 96 + lane);
        eval_group(p0, qx, qy, qz, q2, r1sq, r2sq, base + lane,      lt, cnt1, cnt2, l1, l2);
        eval_group(p1, qx, qy, qz, q2, r1sq, r2sq, base + 32 + lane, lt, cnt1, cnt2, l1, l2);
        eval_group(p2, qx, qy, qz, q2, r1sq, r2sq, base + 64 + lane, lt, cnt1, cnt2, l1, l2);
        eval_group(p3, qx, qy, qz, q2, r1sq, r2sq, base + 96 + lane, lt, cnt1, cnt2, l1, l2);
        if (cnt1 >= NS1 && cnt2 >= NS2) break;
    }
    __syncwarp();

    if (lane == 0) {
        g_state[q * 2 + 0] = min(cnt1, NS1);
        g_state[q * 2 + 1] = min(cnt2, NS2);
    }
    int* dst = g_lists + q * 96;
    for (int j = lane; j < 96; j += 32) dst[j] = s_l[wid][j];
}

// ---------------------------------------------------------------------------
// Kernel 2: phase-2 tail. One block (8 warps) per undone query; the remaining
// NPTS-CAP points split into 8 contiguous segments scanned in parallel; ordered
// per-segment lists merged by prefix offsets (segment order == index order).
// ---------------------------------------------------------------------------
__global__ __launch_bounds__(256) void scan2_kernel() {
    const int q = blockIdx.x;
    const int cnt1 = g_state[q * 2 + 0];
    const int cnt2 = g_state[q * 2 + 1];
    if (cnt1 >= NS1 && cnt2 >= NS2) return;

    __shared__ int lc1[8], lc2[8];
    __shared__ int ll1[8][NS1];
    __shared__ int ll2[8][NS2];

    const int lane = threadIdx.x & 31;
    const int wid  = threadIdx.x >> 5;
    int b;
    const int fi = query_flat_index(q, b);

    const float4* __restrict__ P4 = g_pts4 + (size_t)b * NPTS;
    const float4 qp = __ldg(P4 + fi);
    const float qx = qp.x, qy = qp.y, qz = qp.z, q2 = qp.w;
    float r1sq, r2sq; radii(r1sq, r2sq);

    int c1 = 0, c2 = 0;
    const unsigned lt = (1u << lane) - 1u;
    const int seg0 = CAP + wid * SEG;

    for (int base = seg0; base < seg0 + SEG; base += 64) {
        const float4 p0 = __ldg(P4 + base + lane);
        const float4 p1 = __ldg(P4 + base + 32 + lane);
        eval_group(p0, qx, qy, qz, q2, r1sq, r2sq, base + lane,      lt, c1, c2, ll1[wid], ll2[wid]);
        eval_group(p1, qx, qy, qz, q2, r1sq, r2sq, base + 32 + lane, lt, c1, c2, ll1[wid], ll2[wid]);
        if (c1 >= NS1 && c2 >= NS2) break;
    }
    if (lane == 0) { lc1[wid] = min(c1, NS1); lc2[wid] = min(c2, NS2); }
    __syncthreads();

    int off1 = cnt1, off2 = cnt2;
#pragma unroll
    for (int v = 0; v < 8; v++) {
        if (v < wid) { off1 += lc1[v]; off2 += lc2[v]; }
    }
    const int n1 = lc1[wid], n2 = lc2[wid];
    int* g1 = g_lists + q * 96;
    int* g2 = g1 + NS1;
    for (int j = lane; j < n1; j += 32) { const int p = off1 + j; if (p < NS1) g1[p] = ll1[wid][j]; }
    for (int j = lane; j < n2; j += 32) { const int p = off2 + j; if (p < NS2) g2[p] = ll2[wid][j]; }
    __syncthreads();

    int t1 = cnt1, t2 = cnt2;
#pragma unroll
    for (int v = 0; v < 8; v++) { t1 += lc1[v]; t2 += lc2[v]; }
    t1 = min(t1, NS1); t2 = min(t2, NS2);

    if (wid == 0) {           // pad list1 with first element (or 0 if empty)
        const int f1 = (t1 > 0) ? g1[0] : 0;
        for (int j = t1 + lane; j < NS1; j += 32) g1[j] = f1;
    } else if (wid == 1) {    // pad list2
        const int f2 = (t2 > 0) ? g2[0] : 0;
        for (int j = t2 + lane; j < NS2; j += 32) g2[j] = f2;
    }
}

// ---------------------------------------------------------------------------
// Kernel 3: MLP. 16 queries per 512-thread block (128 blocks = ~1/SM).
// Gather via packed float4; tiny MLPs from smem weights; max-pool via shuffle;
// fused 64->128 linear from transposed smem w3.
// ---------------------------------------------------------------------------
#define INVC 0.9999950000374997f

__device__ __forceinline__ void mlp_point(
    float gx, float gy, float gz, float qx, float qy, float qz,
    const float* __restrict__ sA, const float* __restrict__ scA, const float* __restrict__ biA,
    const float* __restrict__ sB, const float* __restrict__ scB, const float* __restrict__ biB,
    float f[32])
{
    const float x0 = gx - qx, x1 = gy - qy, x2 = gz - qz;
    float a[16];
#pragma unroll
    for (int o = 0; o < 16; o++) {
        const float* w = sA + o * 6;
        float y = x0 * w[0];
        y = fmaf(x1, w[1], y);
        y = fmaf(x2, w[2], y);
        y = fmaf(gx, w[3], y);
        y = fmaf(gy, w[4], y);
        y = fmaf(gz, w[5], y);
        a[o] = fmaxf(fmaf(y, scA[o], biA[o]), 0.0f);
    }
#pragma unroll
    for (int o = 0; o < 32; o++) {
        const float* w = sB + o * 16;
        float y = 0.0f;
#pragma unroll
        for (int c = 0; c < 16; c++) y = fmaf(a[c], w[c], y);
        f[o] = fmaxf(f[o], fmaxf(fmaf(y, scB[o], biB[o]), 0.0f));
    }
}

__device__ __forceinline__ void warp_max32(float f[32]) {
#pragma unroll
    for (int o = 0; o < 32; o++) {
        float v = f[o];
        v = fmaxf(v, __shfl_xor_sync(0xffffffffu, v, 16));
        v = fmaxf(v, __shfl_xor_sync(0xffffffffu, v, 8));
        v = fmaxf(v, __shfl_xor_sync(0xffffffffu, v, 4));
        v = fmaxf(v, __shfl_xor_sync(0xffffffffu, v, 2));
        v = fmaxf(v, __shfl_xor_sync(0xffffffffu, v, 1));
        f[o] = v;
    }
}

__global__ __launch_bounds__(512) void mlp_kernel(
    const float* __restrict__ w1a, const float* __restrict__ g1a, const float* __restrict__ b1a,
    const float* __restrict__ w1b, const float* __restrict__ g1b, const float* __restrict__ b1b,
    const float* __restrict__ w2a, const float* __restrict__ g2a, const float* __restrict__ b2a,
    const float* __restrict__ w2b, const float* __restrict__ g2b, const float* __restrict__ b2b,
    const float* __restrict__ w3,  const float* __restrict__ b3,
    float* __restrict__ out)
{
    __shared__ float s_w1a[96],  s_w2a[96];
    __shared__ float s_w1b[512], s_w2b[512];
    __shared__ float s_sc1a[16], s_bi1a[16], s_sc2a[16], s_bi2a[16];
    __shared__ float s_sc1b[32], s_bi1b[32], s_sc2b[32], s_bi2b[32];
    __shared__ float s_w3t[64 * 129];   // transposed + padded

    const int tid = threadIdx.x;
    for (int i = tid; i < 96; i += 512)  { s_w1a[i] = w1a[i]; s_w2a[i] = w2a[i]; }
    for (int i = tid; i < 512; i += 512) { s_w1b[i] = w1b[i]; s_w2b[i] = w2b[i]; }
    if (tid < 16) {
        s_sc1a[tid] = g1a[tid] * INVC; s_bi1a[tid] = b1a[tid];
        s_sc2a[tid] = g2a[tid] * INVC; s_bi2a[tid] = b2a[tid];
    } else if (tid < 48) {
        const int i = tid - 16;
        s_sc1b[i] = g1b[i] * INVC; s_bi1b[i] = b1b[i];
        s_sc2b[i] = g2b[i] * INVC; s_bi2b[i] = b2b[i];
    }
    // w3 transpose via float4 loads: 2048 float4s per block.
    const float4* __restrict__ w3v = (const float4*)w3;
    for (int i = tid; i < NOUT * 16; i += 512) {
        const float4 v = __ldg(w3v + i);
        const int o  = i >> 4;
        const int c4 = (i & 15) * 4;
        s_w3t[(c4 + 0) * 129 + o] = v.x;
        s_w3t[(c4 + 1) * 129 + o] = v.y;
        s_w3t[(c4 + 2) * 129 + o] = v.z;
        s_w3t[(c4 + 3) * 129 + o] = v.w;
    }
    __syncthreads();

    const int lane = tid & 31;
    const int wid  = tid >> 5;
    const int q    = blockIdx.x * 16 + wid;         // 128 blocks x 16 queries
    int b;
    const int fi = query_flat_index(q, b);

    const float4* __restrict__ P4 = g_pts4 + (size_t)b * NPTS;
    const float4 qp = __ldg(P4 + fi);
    const float qx = qp.x, qy = qp.y, qz = qp.z;

    const int* lst = g_lists + q * 96;
    const int i0 = __ldg(lst + lane);
    const int i1 = __ldg(lst + NS1 + lane);
    const int i2 = __ldg(lst + NS1 + 32 + lane);
    const float4 n0 = __ldg(P4 + i0);
    const float4 n1 = __ldg(P4 + i1);
    const float4 n2 = __ldg(P4 + i2);

    const size_t ob = (size_t)q * NOUT;
    float acc[4];
#pragma unroll
    for (int k = 0; k < 4; k++) acc[k] = __ldg(b3 + lane + 32 * k);

    {   // branch 1 (S=32)
        float f[32];
#pragma unroll
        for (int o = 0; o < 32; o++) f[o] = 0.0f;
        mlp_point(n0.x, n0.y, n0.z, qx, qy, qz, s_w1a, s_sc1a, s_bi1a, s_w1b, s_sc1b, s_bi1b, f);
        warp_max32(f);
#pragma unroll
        for (int k = 0; k < 4; k++) {
            const int o = lane + 32 * k;
            float a = acc[k];
#pragma unroll
            for (int c = 0; c < 32; c++) a = fmaf(f[c], s_w3t[c * 129 + o], a);
            acc[k] = a;
        }
    }
    {   // branch 2 (S=64)
        float f[32];
#pragma unroll
        for (int o = 0; o < 32; o++) f[o] = 0.0f;
        mlp_point(n1.x, n1.y, n1.z, qx, qy, qz, s_w2a, s_sc2a, s_bi2a, s_w2b, s_sc2b, s_bi2b, f);
        mlp_point(n2.x, n2.y, n2.z, qx, qy, qz, s_w2a, s_sc2a, s_bi2a, s_w2b, s_sc2b, s_bi2b, f);
        warp_max32(f);
#pragma unroll
        for (int k = 0; k < 4; k++) {
            const int o = lane + 32 * k;
            float a = acc[k];
#pragma unroll
            for (int c = 0; c < 32; c++) a = fmaf(f[c], s_w3t[(c + 32) * 129 + o], a);
            acc[k] = a;
        }
    }
#pragma unroll
    for (int k = 0; k < 4; k++) out[ob + lane + 32 * k] = acc[k];
}

extern "C" void kernel_launch(void* const* d_in, const int* in_sizes, int n_in,
                              void* d_out, int out_size) {
    const float* pts = (const float*)d_in[0];
    const float* w1a = (const float*)d_in[1];
    const float* g1a = (const float*)d_in[2];
    const float* b1a = (const float*)d_in[3];
    const float* w1b = (const float*)d_in[4];
    const float* g1b = (const float*)d_in[5];
    const float* b1b = (const float*)d_in[6];
    const float* w2a = (const float*)d_in[7];
    const float* g2a = (const float*)d_in[8];
    const float* b2a = (const float*)d_in[9];
    const float* w2b = (const float*)d_in[10];
    const float* g2b = (const float*)d_in[11];
    const float* b2b = (const float*)d_in[12];
    const float* w3  = (const float*)d_in[13];
    const float* b3  = (const float*)d_in[14];
    float* out = (float*)d_out;

    pack_kernel<<<NBATCH * NPTS / 256, 256>>>(pts);
    scan1_kernel<<<NBATCH * NQ / 8, 256>>>();
    scan2_kernel<<<NBATCH * NQ, 256>>>();
    mlp_kernel<<<NBATCH * NQ / 16, 512>>>(w1a, g1a, b1a, w1b, g1b, b1b,
                                          w2a, g2a, b2a, w2b, g2b, b2b, w3, b3, out);
}